// round 14
// baseline (speedup 1.0000x reference)
#include <cuda_runtime.h>
#include <cstdint>

// out[c, i, j] = one_hot[i, c]      for c in [0,4)
// out[c, i, j] = one_hot[j, c-4]    for c in [4,8)
// one_hot: [L, 4] float32, L = 4096; out: [8, L, L] float32 (536.9 MB stores)
//
// FINAL (R8 / .cs variant; 73.79us repeat-measured, DRAM 82.5%):
//  - top planes: one block per contiguous 16KB output row; 1 broadcast load,
//    each thread stores 4 consecutive 4KB segments (STG.128 .cs streaming).
//  - bottom planes: warp-local smem channel stage (4 coalesced LDG.128 ->
//    extract channel -> stride-1 STS -> 1 LDS.128), value reused down a
//    4-row strip of streaming stores.
//
// Ceiling evidence: strided STG, contiguous STG, plane-reorder, TMA bulk
// stores, and .wt write-through ALL pin DRAM at 81.7-82.8% and land in
// 73.8 +- 0.7us -> sustained HBM3e write-stream ceiling (~7.3 TB/s
// wall-clock, 91% of 8 TB/s spec). No kernel-side lever remains: output
// bytes irreducible (poisoned d_out), no store wider than 128b on sm_103a,
// reads fully cache-resident.

#define BLOCK 256
#define ROWS  4
#define SEGS  4          // L4 / BLOCK for L=4096

__global__ __launch_bounds__(BLOCK, 8)
void seq_embed_kernel(const float* __restrict__ oh, float4* __restrict__ out, int L)
{
    const int c  = blockIdx.z;                              // 0..7 plane (uniform per block)
    const int L4 = L >> 2;

    if (c < 4) {
        // One block = one full row (16KB contiguous). Thread stores SEGS
        // consecutive 4KB segments of that row; value loaded once.
        const int row = blockIdx.y * SEGS + blockIdx.x;     // 0..L-1
        const float val = __ldg(&oh[row * 4 + c]);
        const float4 v = make_float4(val, val, val, val);

        float4* p = out + ((size_t)c * L + (size_t)row) * (size_t)L4 + threadIdx.x;
#pragma unroll
        for (int s = 0; s < SEGS; s++) {
            __stcs(p, v);
            p += BLOCK;
        }
    } else {
        // Column one-hot, warp-local staging:
        // 4 coalesced LDG.128/lane -> extract channel -> stride-1 STS into the
        // warp's own 128-float slice -> __syncwarp -> one LDS.128/lane,
        // value reused down a 4-row strip of streaming stores.
        __shared__ float sch[4 * BLOCK];                    // 4 KB, 128 floats/warp
        const int i0 = blockIdx.y * ROWS;                   // row-strip base
        const int j4 = blockIdx.x * BLOCK + threadIdx.x;    // float4 column
        const int cc    = c - 4;
        const int lane  = threadIdx.x & 31;
        const int warp  = threadIdx.x >> 5;
        const int wb4   = blockIdx.x * BLOCK + warp * 32;   // warp-base float4 column
        const int rbase = 4 * wb4;                          // warp-base one_hot row
        const float4* ohf4 = reinterpret_cast<const float4*>(oh);
        float* ws = &sch[warp * 128];

#pragma unroll
        for (int q = 0; q < 4; q++) {
            const float4 rv = __ldg(&ohf4[rbase + q * 32 + lane]);
            ws[q * 32 + lane] =
                (cc & 1) ? ((cc & 2) ? rv.w : rv.y)
                         : ((cc & 2) ? rv.z : rv.x);
        }
        __syncwarp();

        const float4 v = *reinterpret_cast<const float4*>(&ws[4 * lane]);
        float4* p = out + ((size_t)c * L + (size_t)i0) * (size_t)L4 + (size_t)j4;
#pragma unroll
        for (int r = 0; r < ROWS; r++) {
            __stcs(p, v);
            p += L4;
        }
    }
}

extern "C" void kernel_launch(void* const* d_in, const int* in_sizes, int n_in,
                              void* d_out, int out_size)
{
    const float* oh = (const float*)d_in[0];
    const int L  = in_sizes[0] / 4;   // one_hot is [L, 4]
    const int L4 = L >> 2;

    dim3 block(BLOCK);
    dim3 grid(L4 / BLOCK, L / ROWS, 8);   // (4, 1024, 8) = 32768 blocks for L=4096
    seq_embed_kernel<<<grid, block>>>(oh, (float4*)d_out, L);
}

// round 15
// speedup vs baseline: 1.0095x; 1.0095x over previous
#include <cuda_runtime.h>
#include <cstdint>

// out[c, i, j] = one_hot[i, c]      for c in [0,4)
// out[c, i, j] = one_hot[j, c-4]    for c in [4,8)
// one_hot: [L, 4] float32, L = 4096; out: [8, L, L] float32 (536.9 MB stores)
//
// FINAL (R8 / .cs variant; best repeat-measured 73.79us, in-kernel best
// 72.54us / DRAM 83.0% / 6575 GB/s):
//  - top planes: one block per contiguous 16KB output row; 1 broadcast load,
//    each thread stores 4 consecutive 4KB segments (STG.128 .cs streaming).
//  - bottom planes: warp-local smem channel stage (4 coalesced LDG.128 ->
//    extract channel -> stride-1 STS -> 1 LDS.128), value reused down a
//    4-row strip of streaming stores.
//
// Ceiling evidence (complete mechanism matrix): strided STG, contiguous STG,
// plane-reorder, TMA bulk stores, .wt write-through, persistent vs
// oversubscribed grids ALL pin DRAM at 81.7-83.0% and land in 74.1 +- 0.7us
// -> sustained HBM3e write-stream ceiling (~7.3 TB/s wall-clock, 91% of
// 8 TB/s spec). Output bytes irreducible (poisoned d_out), no store wider
// than 128b on sm_103a, reads fully cache-resident. No lever remains.

#define BLOCK 256
#define ROWS  4
#define SEGS  4          // L4 / BLOCK for L=4096

__global__ __launch_bounds__(BLOCK, 8)
void seq_embed_kernel(const float* __restrict__ oh, float4* __restrict__ out, int L)
{
    const int c  = blockIdx.z;                              // 0..7 plane (uniform per block)
    const int L4 = L >> 2;

    if (c < 4) {
        // One block = one full row (16KB contiguous). Thread stores SEGS
        // consecutive 4KB segments of that row; value loaded once.
        const int row = blockIdx.y * SEGS + blockIdx.x;     // 0..L-1
        const float val = __ldg(&oh[row * 4 + c]);
        const float4 v = make_float4(val, val, val, val);

        float4* p = out + ((size_t)c * L + (size_t)row) * (size_t)L4 + threadIdx.x;
#pragma unroll
        for (int s = 0; s < SEGS; s++) {
            __stcs(p, v);
            p += BLOCK;
        }
    } else {
        // Column one-hot, warp-local staging:
        // 4 coalesced LDG.128/lane -> extract channel -> stride-1 STS into the
        // warp's own 128-float slice -> __syncwarp -> one LDS.128/lane,
        // value reused down a 4-row strip of streaming stores.
        __shared__ float sch[4 * BLOCK];                    // 4 KB, 128 floats/warp
        const int i0 = blockIdx.y * ROWS;                   // row-strip base
        const int j4 = blockIdx.x * BLOCK + threadIdx.x;    // float4 column
        const int cc    = c - 4;
        const int lane  = threadIdx.x & 31;
        const int warp  = threadIdx.x >> 5;
        const int wb4   = blockIdx.x * BLOCK + warp * 32;   // warp-base float4 column
        const int rbase = 4 * wb4;                          // warp-base one_hot row
        const float4* ohf4 = reinterpret_cast<const float4*>(oh);
        float* ws = &sch[warp * 128];

#pragma unroll
        for (int q = 0; q < 4; q++) {
            const float4 rv = __ldg(&ohf4[rbase + q * 32 + lane]);
            ws[q * 32 + lane] =
                (cc & 1) ? ((cc & 2) ? rv.w : rv.y)
                         : ((cc & 2) ? rv.z : rv.x);
        }
        __syncwarp();

        const float4 v = *reinterpret_cast<const float4*>(&ws[4 * lane]);
        float4* p = out + ((size_t)c * L + (size_t)i0) * (size_t)L4 + (size_t)j4;
#pragma unroll
        for (int r = 0; r < ROWS; r++) {
            __stcs(p, v);
            p += L4;
        }
    }
}

extern "C" void kernel_launch(void* const* d_in, const int* in_sizes, int n_in,
                              void* d_out, int out_size)
{
    const float* oh = (const float*)d_in[0];
    const int L  = in_sizes[0] / 4;   // one_hot is [L, 4]
    const int L4 = L >> 2;

    dim3 block(BLOCK);
    dim3 grid(L4 / BLOCK, L / ROWS, 8);   // (4, 1024, 8) = 32768 blocks for L=4096
    seq_embed_kernel<<<grid, block>>>(oh, (float4*)d_out, L);
}